// round 5
// baseline (speedup 1.0000x reference)
#include <cuda_runtime.h>
#include <cuda_fp16.h>
#include <cstdint>

// ---------------- problem constants ----------------
#define BATCH    64
#define INCH     8192
#define OUTCH    8192
#define NT       64             // out-channel tile per CTA
#define KT       64             // K tile (64 fp16 = 128B row)
#define NITER    (INCH / KT)    // 128
#define NTHREADS 256
#define NCTAS    (OUTCH / NT)   // 128
#define NSTAGE   4

// per stage: A 64x128B = 8KB, B 64x128B = 8KB
#define STAGE_BYTES 16384
#define SMEM_BYTES  (NSTAGE * STAGE_BYTES)   // 65536

__device__ __half g_xhalf[(size_t)BATCH * INCH];   // single fp16 plane of x
__device__ float g_abssum;

// ---------------- helpers ----------------
__device__ __forceinline__ uint32_t smem_u32(const void* p) {
    uint32_t a;
    asm("{ .reg .u64 t; cvta.to.shared.u64 t, %1; cvt.u32.u64 %0, t; }" : "=r"(a) : "l"(p));
    return a;
}

#define SW128(off) ((off) ^ (((off) >> 3) & 0x70))

// sign(w) as fp16: +1 / -1 / 0
__device__ __forceinline__ uint32_t sgn_f16(float w) {
    uint32_t u = __float_as_uint(w);
    return (w == 0.0f) ? 0u : (0x3C00u | ((u >> 16) & 0x8000u));
}

__device__ __forceinline__ void ldsm_x4(uint32_t* r, uint32_t addr) {
    asm volatile("ldmatrix.sync.aligned.m8n8.x4.shared.b16 {%0,%1,%2,%3}, [%4];"
                 : "=r"(r[0]), "=r"(r[1]), "=r"(r[2]), "=r"(r[3]) : "r"(addr));
}

__device__ __forceinline__ void mma_f16(float* c, const uint32_t* a, const uint32_t* b) {
    asm volatile(
        "mma.sync.aligned.m16n8k16.row.col.f32.f16.f16.f32 "
        "{%0,%1,%2,%3}, {%4,%5,%6,%7}, {%8,%9}, {%0,%1,%2,%3};"
        : "+f"(c[0]), "+f"(c[1]), "+f"(c[2]), "+f"(c[3])
        : "r"(a[0]), "r"(a[1]), "r"(a[2]), "r"(a[3]), "r"(b[0]), "r"(b[1]));
}

__device__ __forceinline__ void cp_async16(uint32_t dst, const void* src) {
    asm volatile("cp.async.cg.shared.global [%0], [%1], 16;"
                 :: "r"(dst), "l"(__cvta_generic_to_global(src)) : "memory");
}
#define CP_COMMIT() asm volatile("cp.async.commit_group;" ::: "memory")
#define CP_WAIT(n)  asm volatile("cp.async.wait_group %0;" :: "n"(n) : "memory")

// ---------------- kernel 0: x -> single fp16 plane ----------------
__global__ void hb_split_kernel(const float* __restrict__ x) {
    int i = blockIdx.x * blockDim.x + threadIdx.x;   // over float4 chunks (131072)
    if (i == 0) g_abssum = 0.0f;
    float4 v = reinterpret_cast<const float4*>(x)[i];
    __half2* hp = reinterpret_cast<__half2*>(g_xhalf);
    hp[i * 2 + 0] = __floats2half2_rn(v.x, v.y);
    hp[i * 2 + 1] = __floats2half2_rn(v.z, v.w);
}

// ---------------- kernel 1: fused sign + mma.sync GEMM + |W| reduce ----------------
__global__ void __launch_bounds__(NTHREADS, 1)
hb_gemm_kernel(const float* __restrict__ W, float* __restrict__ out) {
    extern __shared__ __align__(1024) char smem[];
    const uint32_t sb = smem_u32(smem);

    const int tid  = threadIdx.x;
    const int lane = tid & 31;
    const int wid  = tid >> 5;
    const int wm   = wid & 3;          // 4 warps along M (16 rows each)
    const int wn   = wid >> 2;         // 2 warps along N (32 cols each)
    const int n0   = blockIdx.x * NT;
    const int nw   = wn * 32;
    const int mw   = wm * 16;

#define A_OFF(s) (sb + (uint32_t)(s) * STAGE_BYTES)
#define B_OFF(s) (sb + (uint32_t)(s) * STAGE_BYTES + 8192)

    float c[4][4];                     // [n-tile][frag]
#pragma unroll
    for (int nt = 0; nt < 4; nt++)
#pragma unroll
        for (int r = 0; r < 4; r++) c[nt][r] = 0.0f;

    float absacc = 0.0f;
    float4 wv[2][4];                   // 2-deep register lookahead, 16 floats each

    // ldmatrix per-lane coordinates
    const int arow  = mw + (lane & 15);
    const int ac8   = lane >> 4;
    const int brow0 = nw +      (lane & 7) + ((lane >> 4) << 3);
    const int brow1 = nw + 16 + (lane & 7) + ((lane >> 4) << 3);
    const int bc8   = (lane >> 3) & 1;

    // W load/store coords: 2 groups of 8 contiguous floats per thread
    int wrow[2], wkc[2];
#pragma unroll
    for (int g = 0; g < 2; g++) { int cid = tid + g * NTHREADS; wrow[g] = cid >> 3; wkc[g] = cid & 7; }
    // A cp.async coords: 2 groups of 16B per thread (64 rows x 8 chunks = 512)
    int xrow[2], xc8[2];
#pragma unroll
    for (int g = 0; g < 2; g++) { int cid = tid + g * NTHREADS; xrow[g] = cid >> 3; xc8[g] = cid & 7; }

#define LOADW(it, buf) do { \
    int _k0 = (it) * KT; \
    _Pragma("unroll") \
    for (int g = 0; g < 2; g++) { \
        const float4* p = reinterpret_cast<const float4*>( \
            W + (size_t)(n0 + wrow[g]) * INCH + _k0 + wkc[g] * 8); \
        wv[buf][2*g]   = p[0]; \
        wv[buf][2*g+1] = p[1]; \
    } \
} while (0)

#define CPA(it, st) do { \
    int _k0 = (it) * KT; \
    _Pragma("unroll") \
    for (int g = 0; g < 2; g++) { \
        const __half* src = g_xhalf + (size_t)xrow[g] * INCH + _k0 + xc8[g] * 8; \
        cp_async16(A_OFF(st) + SW128((uint32_t)(xrow[g] * 128 + xc8[g] * 16)), src); \
    } \
    CP_COMMIT(); \
} while (0)

#define STSW(st, buf) do { \
    _Pragma("unroll") \
    for (int g = 0; g < 2; g++) { \
        float f0 = wv[buf][2*g].x, f1 = wv[buf][2*g].y, f2 = wv[buf][2*g].z, f3 = wv[buf][2*g].w; \
        float f4 = wv[buf][2*g+1].x, f5 = wv[buf][2*g+1].y, f6 = wv[buf][2*g+1].z, f7 = wv[buf][2*g+1].w; \
        absacc += fabsf(f0)+fabsf(f1)+fabsf(f2)+fabsf(f3)+fabsf(f4)+fabsf(f5)+fabsf(f6)+fabsf(f7); \
        uint32_t p0 = sgn_f16(f0) | (sgn_f16(f1) << 16); \
        uint32_t p1 = sgn_f16(f2) | (sgn_f16(f3) << 16); \
        uint32_t p2 = sgn_f16(f4) | (sgn_f16(f5) << 16); \
        uint32_t p3 = sgn_f16(f6) | (sgn_f16(f7) << 16); \
        asm volatile("st.shared.v4.b32 [%0], {%1,%2,%3,%4};" \
                     :: "r"(B_OFF(st) + SW128((uint32_t)(wrow[g] * 128 + wkc[g] * 16))), \
                        "r"(p0), "r"(p1), "r"(p2), "r"(p3) : "memory"); \
    } \
} while (0)

#define COMPUTE(st) do { \
    const uint32_t _A = A_OFF(st), _B = B_OFF(st); \
    _Pragma("unroll") \
    for (int ks = 0; ks < 4; ks++) { \
        uint32_t bf0[4], bf1[4], af[4]; \
        ldsm_x4(af,  _A + SW128((uint32_t)(arow  * 128 + ks * 32 + ac8 * 16))); \
        ldsm_x4(bf0, _B + SW128((uint32_t)(brow0 * 128 + ks * 32 + bc8 * 16))); \
        ldsm_x4(bf1, _B + SW128((uint32_t)(brow1 * 128 + ks * 32 + bc8 * 16))); \
        mma_f16(c[0], af, bf0); mma_f16(c[1], af, bf0 + 2); \
        mma_f16(c[2], af, bf1); mma_f16(c[3], af, bf1 + 2); \
    } \
} while (0)

    // ---- prologue: B stages 0..2 converted, A stages 0..2 in flight, W(2) staged ----
    LOADW(0, 0); STSW(0, 0);
    LOADW(1, 1); STSW(1, 1);
    LOADW(2, 0);                     // consumed by STSW(2) at iter 0
    CPA(0, 0); CPA(1, 1); CPA(2, 2);
    CP_WAIT(2);                      // stage 0 A resident
    __syncthreads();

    // ---- main loop: one sync per iter ----
    for (int it = 0; it < NITER; ++it) {
        if (it + 3 < NITER) { LOADW(it + 3, (it + 3) & 1); CPA(it + 3, (it + 3) & 3); }
        COMPUTE(it & 3);
        if (it + 2 < NITER) STSW((it + 2) & 3, (it + 2) & 1);
        if (it + 1 < NITER) {
            if (it + 3 < NITER) CP_WAIT(2); else CP_WAIT(0);
            __syncthreads();
        }
    }

    // |W| warp reduce + one atomic per warp
#pragma unroll
    for (int o = 16; o > 0; o >>= 1) absacc += __shfl_xor_sync(0xFFFFFFFFu, absacc, o);
    if (lane == 0) atomicAdd(&g_abssum, absacc);

    // epilogue: registers -> global (unscaled; kernel 2 applies mean|W|)
#pragma unroll
    for (int nt = 0; nt < 4; nt++) {
        int col = n0 + nw + nt * 8 + (lane & 3) * 2;
        int r0  = mw + (lane >> 2);
        *reinterpret_cast<float2*>(out + (size_t)r0 * OUTCH + col) =
            make_float2(c[nt][0], c[nt][1]);
        *reinterpret_cast<float2*>(out + (size_t)(r0 + 8) * OUTCH + col) =
            make_float2(c[nt][2], c[nt][3]);
    }

#undef LOADW
#undef CPA
#undef STSW
#undef COMPUTE
#undef A_OFF
#undef B_OFF
}

// ---------------- kernel 2: apply scale = mean(|W|) ----------------
__global__ void hb_scale_kernel(float* __restrict__ out) {
    float s = g_abssum * (1.0f / ((float)INCH * (float)OUTCH));
    int i = blockIdx.x * blockDim.x + threadIdx.x;
    float4* o = reinterpret_cast<float4*>(out);
    float4 v = o[i];
    v.x *= s; v.y *= s; v.z *= s; v.w *= s;
    o[i] = v;
}

// ---------------- launch ----------------
extern "C" void kernel_launch(void* const* d_in, const int* in_sizes, int n_in,
                              void* d_out, int out_size) {
    const float* x = (const float*)d_in[0];
    const float* w = (const float*)d_in[1];
    if (n_in >= 2 && in_sizes[0] != BATCH * INCH) { const float* t = x; x = w; w = t; }
    float* out = (float*)d_out;

    cudaFuncSetAttribute(hb_gemm_kernel,
                         cudaFuncAttributeMaxDynamicSharedMemorySize, SMEM_BYTES);

    hb_split_kernel<<<(BATCH * INCH / 4) / 256, 256>>>(x);
    hb_gemm_kernel<<<NCTAS, NTHREADS, SMEM_BYTES>>>(w, out);
    hb_scale_kernel<<<(BATCH * OUTCH / 4) / 256, 256>>>(out);
}

// round 6
// speedup vs baseline: 2.0746x; 2.0746x over previous
#include <cuda_runtime.h>
#include <cuda_fp16.h>
#include <cstdint>

// ---------------- problem constants ----------------
#define BATCH    64
#define INCH     8192
#define OUTCH    8192
#define NT       64             // out-channel tile per CTA
#define KT       64             // K tile (64 fp16 = 128B row)
#define NITER    (INCH / KT)    // 128
#define NTHREADS 256
#define NCTAS    (OUTCH / NT)   // 128

// W fp32 ring: 5 stages x 64 rows x 320B (padded pitch) = 102400
// A fp16 ring: 5 stages x 8192
// B sign ring: 2 stages x 8192
#define W_PITCH     320
#define W_STAGE     (64 * W_PITCH)
#define SMEM_W      0
#define SMEM_A      (5 * W_STAGE)
#define SMEM_B      (SMEM_A + 5 * 8192)
#define SMEM_BYTES  (SMEM_B + 2 * 8192)   // 159744

__device__ __half g_xhalf[(size_t)BATCH * INCH];   // single fp16 plane of x
__device__ float g_abssum;

// ---------------- helpers ----------------
__device__ __forceinline__ uint32_t smem_u32(const void* p) {
    uint32_t a;
    asm("{ .reg .u64 t; cvta.to.shared.u64 t, %1; cvt.u32.u64 %0, t; }" : "=r"(a) : "l"(p));
    return a;
}

#define SW128(off) ((off) ^ (((off) >> 3) & 0x70))

// sign(w) as fp16: +1 / -1 / 0
__device__ __forceinline__ uint32_t sgn_f16(float w) {
    uint32_t u = __float_as_uint(w);
    return (w == 0.0f) ? 0u : (0x3C00u | ((u >> 16) & 0x8000u));
}

__device__ __forceinline__ void ldsm_x4(uint32_t* r, uint32_t addr) {
    asm volatile("ldmatrix.sync.aligned.m8n8.x4.shared.b16 {%0,%1,%2,%3}, [%4];"
                 : "=r"(r[0]), "=r"(r[1]), "=r"(r[2]), "=r"(r[3]) : "r"(addr));
}

__device__ __forceinline__ void mma_f16(float* c, const uint32_t* a, const uint32_t* b) {
    asm volatile(
        "mma.sync.aligned.m16n8k16.row.col.f32.f16.f16.f32 "
        "{%0,%1,%2,%3}, {%4,%5,%6,%7}, {%8,%9}, {%0,%1,%2,%3};"
        : "+f"(c[0]), "+f"(c[1]), "+f"(c[2]), "+f"(c[3])
        : "r"(a[0]), "r"(a[1]), "r"(a[2]), "r"(a[3]), "r"(b[0]), "r"(b[1]));
}

__device__ __forceinline__ void cp_async16(uint32_t dst, const void* src) {
    asm volatile("cp.async.cg.shared.global [%0], [%1], 16;"
                 :: "r"(dst), "l"(__cvta_generic_to_global(src)) : "memory");
}
#define CP_COMMIT() asm volatile("cp.async.commit_group;" ::: "memory")
#define CP_WAIT(n)  asm volatile("cp.async.wait_group %0;" :: "n"(n) : "memory")

// ---------------- kernel 0: x -> single fp16 plane ----------------
__global__ void hb_split_kernel(const float* __restrict__ x) {
    int i = blockIdx.x * blockDim.x + threadIdx.x;   // over float4 chunks (131072)
    if (i == 0) g_abssum = 0.0f;
    float4 v = reinterpret_cast<const float4*>(x)[i];
    __half2* hp = reinterpret_cast<__half2*>(g_xhalf);
    hp[i * 2 + 0] = __floats2half2_rn(v.x, v.y);
    hp[i * 2 + 1] = __floats2half2_rn(v.z, v.w);
}

// ---------------- kernel 1: fused sign + mma.sync GEMM + |W| reduce ----------------
__global__ void __launch_bounds__(NTHREADS, 1)
hb_gemm_kernel(const float* __restrict__ W, float* __restrict__ out) {
    extern __shared__ __align__(1024) char smem[];
    const uint32_t sb = smem_u32(smem);

    const int tid  = threadIdx.x;
    const int lane = tid & 31;
    const int wid  = tid >> 5;
    const int wm   = wid & 3;          // 4 warps along M (16 rows each)
    const int wn   = wid >> 2;         // 2 warps along N (32 cols each)
    const int n0   = blockIdx.x * NT;
    const int nw   = wn * 32;
    const int mw   = wm * 16;

#define W_OFF(s) (sb + SMEM_W + (uint32_t)(s) * W_STAGE)
#define A_OFF(s) (sb + SMEM_A + (uint32_t)(s) * 8192u)
#define B_OFF(s) (sb + SMEM_B + (uint32_t)(s) * 8192u)

    float c[4][4];                     // [n-tile][frag]
#pragma unroll
    for (int nt = 0; nt < 4; nt++)
#pragma unroll
        for (int r = 0; r < 4; r++) c[nt][r] = 0.0f;

    float absacc = 0.0f;

    // ldmatrix per-lane coordinates
    const int arow  = mw + (lane & 15);
    const int ac8   = lane >> 4;
    const int brow0 = nw +      (lane & 7) + ((lane >> 4) << 3);
    const int brow1 = nw + 16 + (lane & 7) + ((lane >> 4) << 3);
    const int bc8   = (lane >> 3) & 1;

    // W cp.async coords: 4 groups of 16B per thread (64 rows x 16 chunks)
    int wr4[4], wc4[4];
#pragma unroll
    for (int g = 0; g < 4; g++) { int cid = tid + g * NTHREADS; wr4[g] = cid >> 4; wc4[g] = cid & 15; }
    // A cp.async coords: 2 groups of 16B per thread (64 rows x 8 chunks)
    int xr2[2], xc2[2];
#pragma unroll
    for (int g = 0; g < 2; g++) { int cid = tid + g * NTHREADS; xr2[g] = cid >> 3; xc2[g] = cid & 7; }
    // convert-pass coords: thread handles quarter-row (16 floats)
    const int crow = tid >> 2;
    const int cqc  = tid & 3;

#define CPW(it, st) do { \
    int _k0 = (it) * KT; \
    _Pragma("unroll") \
    for (int g = 0; g < 4; g++) \
        cp_async16(W_OFF(st) + (uint32_t)(wr4[g] * W_PITCH + wc4[g] * 16), \
                   W + (size_t)(n0 + wr4[g]) * INCH + _k0 + wc4[g] * 4); \
} while (0)

#define CPA(it, st) do { \
    int _k0 = (it) * KT; \
    _Pragma("unroll") \
    for (int g = 0; g < 2; g++) \
        cp_async16(A_OFF(st) + SW128((uint32_t)(xr2[g] * 128 + xc2[g] * 16)), \
                   g_xhalf + (size_t)xr2[g] * INCH + _k0 + xc2[g] * 8); \
} while (0)

#define CONVERT(st, bp) do { \
    const uint32_t _W = W_OFF(st) + (uint32_t)(crow * W_PITCH + cqc * 64); \
    const uint32_t _B = B_OFF(bp); \
    float f[16]; \
    _Pragma("unroll") \
    for (int j = 0; j < 4; j++) \
        asm volatile("ld.shared.v4.f32 {%0,%1,%2,%3}, [%4];" \
                     : "=f"(f[4*j]), "=f"(f[4*j+1]), "=f"(f[4*j+2]), "=f"(f[4*j+3]) \
                     : "r"(_W + j * 16)); \
    _Pragma("unroll") \
    for (int j = 0; j < 16; j++) absacc += fabsf(f[j]); \
    uint32_t p[8]; \
    _Pragma("unroll") \
    for (int j = 0; j < 8; j++) p[j] = sgn_f16(f[2*j]) | (sgn_f16(f[2*j+1]) << 16); \
    uint32_t _bo = (uint32_t)(crow * 128 + cqc * 32); \
    asm volatile("st.shared.v4.b32 [%0], {%1,%2,%3,%4};" \
                 :: "r"(_B + SW128(_bo)), "r"(p[0]), "r"(p[1]), "r"(p[2]), "r"(p[3]) : "memory"); \
    asm volatile("st.shared.v4.b32 [%0], {%1,%2,%3,%4};" \
                 :: "r"(_B + SW128(_bo + 16)), "r"(p[4]), "r"(p[5]), "r"(p[6]), "r"(p[7]) : "memory"); \
} while (0)

#define COMPUTE(st, bp) do { \
    const uint32_t _A = A_OFF(st), _B = B_OFF(bp); \
    _Pragma("unroll") \
    for (int ks = 0; ks < 4; ks++) { \
        uint32_t bf0[4], bf1[4], af[4]; \
        ldsm_x4(af,  _A + SW128((uint32_t)(arow  * 128 + ks * 32 + ac8 * 16))); \
        ldsm_x4(bf0, _B + SW128((uint32_t)(brow0 * 128 + ks * 32 + bc8 * 16))); \
        ldsm_x4(bf1, _B + SW128((uint32_t)(brow1 * 128 + ks * 32 + bc8 * 16))); \
        mma_f16(c[0], af, bf0); mma_f16(c[1], af, bf0 + 2); \
        mma_f16(c[2], af, bf1); mma_f16(c[3], af, bf1 + 2); \
    } \
} while (0)

    // ---- prologue: stages 0..2 in flight ----
    CPW(0, 0); CPA(0, 0); CP_COMMIT();
    CPW(1, 1); CPA(1, 1); CP_COMMIT();
    CPW(2, 2); CPA(2, 2); CP_COMMIT();
    CP_WAIT(2);                 // stage 0 resident
    __syncthreads();
    CONVERT(0, 0);              // W0 -> Bsign(0)

    // ---- main loop: one sync per iter ----
    int ws = 3, rcur = 0;
    uint32_t bpar = 0;
    for (int it = 0; it < NITER; ++it) {
        int rs1 = (rcur + 1 == 5) ? 0 : rcur + 1;
        if (it + 3 < NITER) {
            CPW(it + 3, ws); CPA(it + 3, ws); CP_COMMIT();
            ws = (ws + 1 == 5) ? 0 : ws + 1;
        }
        if (it + 3 < NITER)      CP_WAIT(2);
        else if (it + 2 < NITER) CP_WAIT(1);
        else                     CP_WAIT(0);
        __syncthreads();
        if (it + 1 < NITER) CONVERT(rs1, bpar ^ 1u);
        COMPUTE(rcur, bpar);
        rcur = rs1; bpar ^= 1u;
    }

    // |W| warp reduce + one atomic per warp
#pragma unroll
    for (int o = 16; o > 0; o >>= 1) absacc += __shfl_xor_sync(0xFFFFFFFFu, absacc, o);
    if (lane == 0) atomicAdd(&g_abssum, absacc);

    // epilogue: registers -> global (unscaled; kernel 2 applies mean|W|)
#pragma unroll
    for (int nt = 0; nt < 4; nt++) {
        int col = n0 + nw + nt * 8 + (lane & 3) * 2;
        int r0  = mw + (lane >> 2);
        *reinterpret_cast<float2*>(out + (size_t)r0 * OUTCH + col) =
            make_float2(c[nt][0], c[nt][1]);
        *reinterpret_cast<float2*>(out + (size_t)(r0 + 8) * OUTCH + col) =
            make_float2(c[nt][2], c[nt][3]);
    }

#undef CPW
#undef CPA
#undef CONVERT
#undef COMPUTE
#undef W_OFF
#undef A_OFF
#undef B_OFF
}

// ---------------- kernel 2: apply scale = mean(|W|) ----------------
__global__ void hb_scale_kernel(float* __restrict__ out) {
    float s = g_abssum * (1.0f / ((float)INCH * (float)OUTCH));
    int i = blockIdx.x * blockDim.x + threadIdx.x;
    float4* o = reinterpret_cast<float4*>(out);
    float4 v = o[i];
    v.x *= s; v.y *= s; v.z *= s; v.w *= s;
    o[i] = v;
}

// ---------------- launch ----------------
extern "C" void kernel_launch(void* const* d_in, const int* in_sizes, int n_in,
                              void* d_out, int out_size) {
    const float* x = (const float*)d_in[0];
    const float* w = (const float*)d_in[1];
    if (n_in >= 2 && in_sizes[0] != BATCH * INCH) { const float* t = x; x = w; w = t; }
    float* out = (float*)d_out;

    cudaFuncSetAttribute(hb_gemm_kernel,
                         cudaFuncAttributeMaxDynamicSharedMemorySize, SMEM_BYTES);

    hb_split_kernel<<<(BATCH * INCH / 4) / 256, 256>>>(x);
    hb_gemm_kernel<<<NCTAS, NTHREADS, SMEM_BYTES>>>(w, out);
    hb_scale_kernel<<<(BATCH * OUTCH / 4) / 256, 256>>>(out);
}

// round 7
// speedup vs baseline: 2.1705x; 1.0462x over previous
#include <cuda_runtime.h>
#include <cuda_fp16.h>
#include <cstdint>

// ---------------- problem constants ----------------
#define BATCH    64
#define INCH     8192
#define OUTCH    8192
#define NT       64             // out-channel tile per CTA
#define KT       64             // K tile (64 fp16 = 128B row)
#define NITER    (INCH / KT)    // 128
#define NTHREADS 256
#define NCTAS    (OUTCH / NT)   // 128

// W fp32 ring: 4 stages x 64 rows x 320B pitch = 81920
// A fp16 ring: 4 stages x 8192 ; B sign ring: 2 stages x 8192
#define W_PITCH     320
#define W_STAGE     (64 * W_PITCH)
#define SMEM_W      0
#define SMEM_A      (4 * W_STAGE)            // 81920
#define SMEM_B      (SMEM_A + 4 * 8192)      // 114688
#define SMEM_BYTES  (SMEM_B + 2 * 8192)      // 131072

__device__ __half g_xhalf[(size_t)BATCH * INCH];   // fp16 plane of x
__device__ float g_abssum;
__device__ int   g_done;

// ---------------- helpers ----------------
__device__ __forceinline__ uint32_t smem_u32(const void* p) {
    uint32_t a;
    asm("{ .reg .u64 t; cvta.to.shared.u64 t, %1; cvt.u32.u64 %0, t; }" : "=r"(a) : "l"(p));
    return a;
}

#define SW128(off) ((off) ^ (((off) >> 3) & 0x70))

// sign(w) as fp16: +1 / -1 / 0
__device__ __forceinline__ uint32_t sgn_f16(float w) {
    uint32_t u = __float_as_uint(w);
    return (w == 0.0f) ? 0u : (0x3C00u | ((u >> 16) & 0x8000u));
}

__device__ __forceinline__ void ldsm_x4(uint32_t* r, uint32_t addr) {
    asm volatile("ldmatrix.sync.aligned.m8n8.x4.shared.b16 {%0,%1,%2,%3}, [%4];"
                 : "=r"(r[0]), "=r"(r[1]), "=r"(r[2]), "=r"(r[3]) : "r"(addr));
}

__device__ __forceinline__ void mma_f16(float* c, const uint32_t* a, const uint32_t* b) {
    asm volatile(
        "mma.sync.aligned.m16n8k16.row.col.f32.f16.f16.f32 "
        "{%0,%1,%2,%3}, {%4,%5,%6,%7}, {%8,%9}, {%0,%1,%2,%3};"
        : "+f"(c[0]), "+f"(c[1]), "+f"(c[2]), "+f"(c[3])
        : "r"(a[0]), "r"(a[1]), "r"(a[2]), "r"(a[3]), "r"(b[0]), "r"(b[1]));
}

__device__ __forceinline__ void cp_async16(uint32_t dst, const void* src) {
    asm volatile("cp.async.cg.shared.global [%0], [%1], 16;"
                 :: "r"(dst), "l"(__cvta_generic_to_global(src)) : "memory");
}
#define CP_COMMIT() asm volatile("cp.async.commit_group;" ::: "memory")
#define CP_WAIT(n)  asm volatile("cp.async.wait_group %0;" :: "n"(n) : "memory")

// ---------------- kernel 0: x -> fp16 plane, reset globals ----------------
__global__ void hb_split_kernel(const float* __restrict__ x) {
    int i = blockIdx.x * blockDim.x + threadIdx.x;   // over float2 chunks (262144)
    if (i == 0) { g_abssum = 0.0f; g_done = 0; }
    float2 v = reinterpret_cast<const float2*>(x)[i];
    reinterpret_cast<__half2*>(g_xhalf)[i] = __floats2half2_rn(v.x, v.y);
}

// ---------------- kernel 1: fused sign + GEMM + |W| reduce + scale ----------------
__global__ void __launch_bounds__(NTHREADS, 1)
hb_gemm_kernel(const float* __restrict__ W, float* __restrict__ out) {
    extern __shared__ __align__(1024) char smem[];
    const uint32_t sb = smem_u32(smem);

    const int tid  = threadIdx.x;
    const int lane = tid & 31;
    const int wid  = tid >> 5;
    const int wn   = wid & 1;          // 2 warps along N (n32 each)
    const int kh   = wid >> 1;         // 4 k16-quarters; this warp's ks
    const int n0   = blockIdx.x * NT;
    const int nw   = wn * 32;

#define W_OFF(s) (sb + SMEM_W + (uint32_t)(s) * W_STAGE)
#define A_OFF(s) (sb + SMEM_A + (uint32_t)(s) * 8192u)
#define B_OFF(s) (sb + SMEM_B + (uint32_t)(s) * 8192u)

    float c[4][4][4];                  // [m-tile][n-tile][frag], warp tile m64 x n32
#pragma unroll
    for (int mt = 0; mt < 4; mt++)
#pragma unroll
        for (int nt = 0; nt < 4; nt++)
#pragma unroll
            for (int r = 0; r < 4; r++) c[mt][nt][r] = 0.0f;

    float absacc = 0.0f;

    // ldmatrix per-lane coordinates
    const int ar    = lane & 15;
    const int ac8   = lane >> 4;
    const int brow0 = nw +      (lane & 7) + ((lane >> 4) << 3);
    const int brow1 = nw + 16 + (lane & 7) + ((lane >> 4) << 3);
    const int bc8   = (lane >> 3) & 1;

    // W cp.async coords: 4 x 16B per thread (64 rows x 16 chunks)
    int wr4[4], wc4[4];
#pragma unroll
    for (int g = 0; g < 4; g++) { int cid = tid + g * NTHREADS; wr4[g] = cid >> 4; wc4[g] = cid & 15; }
    // A cp.async coords: 2 x 16B per thread (64 rows x 8 chunks)
    int xr2[2], xc2[2];
#pragma unroll
    for (int g = 0; g < 2; g++) { int cid = tid + g * NTHREADS; xr2[g] = cid >> 3; xc2[g] = cid & 7; }
    // convert-pass coords: thread handles quarter-row (16 floats)
    const int crow = tid >> 2;
    const int cqc  = tid & 3;

#define CPW(it, st) do { \
    int _k0 = (it) * KT; \
    _Pragma("unroll") \
    for (int g = 0; g < 4; g++) \
        cp_async16(W_OFF(st) + (uint32_t)(wr4[g] * W_PITCH + wc4[g] * 16), \
                   W + (size_t)(n0 + wr4[g]) * INCH + _k0 + wc4[g] * 4); \
} while (0)

#define CPA(it, st) do { \
    int _k0 = (it) * KT; \
    _Pragma("unroll") \
    for (int g = 0; g < 2; g++) \
        cp_async16(A_OFF(st) + SW128((uint32_t)(xr2[g] * 128 + xc2[g] * 16)), \
                   g_xhalf + (size_t)xr2[g] * INCH + _k0 + xc2[g] * 8); \
} while (0)

#define CONVERT(st, bp) do { \
    const uint32_t _W = W_OFF(st) + (uint32_t)(crow * W_PITCH + cqc * 64); \
    const uint32_t _B = B_OFF(bp); \
    float f[16]; \
    _Pragma("unroll") \
    for (int j = 0; j < 4; j++) \
        asm volatile("ld.shared.v4.f32 {%0,%1,%2,%3}, [%4];" \
                     : "=f"(f[4*j]), "=f"(f[4*j+1]), "=f"(f[4*j+2]), "=f"(f[4*j+3]) \
                     : "r"(_W + j * 16)); \
    _Pragma("unroll") \
    for (int j = 0; j < 16; j++) absacc += fabsf(f[j]); \
    uint32_t p[8]; \
    _Pragma("unroll") \
    for (int j = 0; j < 8; j++) p[j] = sgn_f16(f[2*j]) | (sgn_f16(f[2*j+1]) << 16); \
    uint32_t _bo = (uint32_t)(crow * 128 + cqc * 32); \
    asm volatile("st.shared.v4.b32 [%0], {%1,%2,%3,%4};" \
                 :: "r"(_B + SW128(_bo)), "r"(p[0]), "r"(p[1]), "r"(p[2]), "r"(p[3]) : "memory"); \
    asm volatile("st.shared.v4.b32 [%0], {%1,%2,%3,%4};" \
                 :: "r"(_B + SW128(_bo + 16)), "r"(p[4]), "r"(p[5]), "r"(p[6]), "r"(p[7]) : "memory"); \
} while (0)

#define COMPUTE(st, bp) do { \
    const uint32_t _A = A_OFF(st), _B = B_OFF(bp); \
    uint32_t af[16], bf[8]; \
    ldsm_x4(bf,     _B + SW128((uint32_t)(brow0 * 128 + kh * 32 + bc8 * 16))); \
    ldsm_x4(bf + 4, _B + SW128((uint32_t)(brow1 * 128 + kh * 32 + bc8 * 16))); \
    _Pragma("unroll") \
    for (int mt = 0; mt < 4; mt++) \
        ldsm_x4(af + 4 * mt, _A + SW128((uint32_t)((mt * 16 + ar) * 128 + kh * 32 + ac8 * 16))); \
    _Pragma("unroll") \
    for (int mt = 0; mt < 4; mt++) { \
        mma_f16(c[mt][0], af + 4 * mt, bf); \
        mma_f16(c[mt][1], af + 4 * mt, bf + 2); \
        mma_f16(c[mt][2], af + 4 * mt, bf + 4); \
        mma_f16(c[mt][3], af + 4 * mt, bf + 6); \
    } \
} while (0)

    // ---- prologue: stages 0..2 in flight ----
    CPW(0, 0); CPA(0, 0); CP_COMMIT();
    CPW(1, 1); CPA(1, 1); CP_COMMIT();
    CPW(2, 2); CPA(2, 2); CP_COMMIT();
    CP_WAIT(2);                 // stage 0 resident
    __syncthreads();
    CONVERT(0, 0);              // W0 -> Bsign(0)

    // ---- main loop: one sync per iter ----
    int ws = 3, rcur = 0;
    uint32_t bpar = 0;
    for (int it = 0; it < NITER; ++it) {
        int rs1 = (rcur + 1) & 3;
        if (it + 3 < NITER) {
            CPW(it + 3, ws); CPA(it + 3, ws); CP_COMMIT();
            ws = (ws + 1) & 3;
        }
        if (it + 3 < NITER)      CP_WAIT(2);
        else if (it + 2 < NITER) CP_WAIT(1);
        else                     CP_WAIT(0);
        __syncthreads();
        if (it + 1 < NITER) CONVERT(rs1, bpar ^ 1u);
        COMPUTE(rcur, bpar);
        rcur = rs1; bpar ^= 1u;
    }

    // ---- |W| reduce: warp -> CTA ----
#pragma unroll
    for (int o = 16; o > 0; o >>= 1) absacc += __shfl_xor_sync(0xFFFFFFFFu, absacc, o);
    __syncthreads();  // rings dead; smem reused below
    float* comb = reinterpret_cast<float*>(smem);           // 3 x 4096 floats (48KB)
    float* wsum = reinterpret_cast<float*>(smem + 64512);   // 8 floats
    if (lane == 0) wsum[wid] = absacc;

    // ---- kh>0 warps publish partial accumulators ----
    if (kh > 0) {
        float* blk = comb + (kh - 1) * 4096;
#pragma unroll
        for (int mt = 0; mt < 4; mt++)
#pragma unroll
            for (int nt = 0; nt < 4; nt++) {
                int r0 = mt * 16 + (lane >> 2);
                int cl = nw + nt * 8 + (lane & 3) * 2;
                blk[r0 * 64 + cl]       = c[mt][nt][0];
                blk[r0 * 64 + cl + 1]   = c[mt][nt][1];
                blk[(r0 + 8) * 64 + cl]     = c[mt][nt][2];
                blk[(r0 + 8) * 64 + cl + 1] = c[mt][nt][3];
            }
    }
    __syncthreads();

    // ---- global barrier across all CTAs, then pick up final abs-sum ----
    if (tid == 0) {
        float ctasum = 0.0f;
#pragma unroll
        for (int j = 0; j < 8; j++) ctasum += wsum[j];
        atomicAdd(&g_abssum, ctasum);
        __threadfence();
        atomicAdd(&g_done, 1);
        while (*((volatile int*)&g_done) < NCTAS) __nanosleep(64);
    }
    __syncthreads();
    const float s = (*((volatile float*)&g_abssum)) * (1.0f / ((float)INCH * (float)OUTCH));

    // ---- kh==0 warps combine 4 partials, scale, store ----
    if (kh == 0) {
#pragma unroll
        for (int mt = 0; mt < 4; mt++)
#pragma unroll
            for (int nt = 0; nt < 4; nt++) {
                int r0 = mt * 16 + (lane >> 2);
                int cl = nw + nt * 8 + (lane & 3) * 2;
                float v0 = c[mt][nt][0], v1 = c[mt][nt][1];
                float v2 = c[mt][nt][2], v3 = c[mt][nt][3];
#pragma unroll
                for (int q = 0; q < 3; q++) {
                    const float* blk = comb + q * 4096;
                    v0 += blk[r0 * 64 + cl];
                    v1 += blk[r0 * 64 + cl + 1];
                    v2 += blk[(r0 + 8) * 64 + cl];
                    v3 += blk[(r0 + 8) * 64 + cl + 1];
                }
                *reinterpret_cast<float2*>(out + (size_t)r0 * OUTCH + n0 + cl) =
                    make_float2(v0 * s, v1 * s);
                *reinterpret_cast<float2*>(out + (size_t)(r0 + 8) * OUTCH + n0 + cl) =
                    make_float2(v2 * s, v3 * s);
            }
    }

#undef CPW
#undef CPA
#undef CONVERT
#undef COMPUTE
#undef W_OFF
#undef A_OFF
#undef B_OFF
}

// ---------------- launch ----------------
extern "C" void kernel_launch(void* const* d_in, const int* in_sizes, int n_in,
                              void* d_out, int out_size) {
    const float* x = (const float*)d_in[0];
    const float* w = (const float*)d_in[1];
    if (n_in >= 2 && in_sizes[0] != BATCH * INCH) { const float* t = x; x = w; w = t; }
    float* out = (float*)d_out;

    cudaFuncSetAttribute(hb_gemm_kernel,
                         cudaFuncAttributeMaxDynamicSharedMemorySize, SMEM_BYTES);

    hb_split_kernel<<<(BATCH * INCH / 2) / 256, 256>>>(x);
    hb_gemm_kernel<<<NCTAS, NTHREADS, SMEM_BYTES>>>(w, out);
}

// round 8
// speedup vs baseline: 2.6631x; 1.2270x over previous
#include <cuda_runtime.h>
#include <cuda_fp16.h>
#include <cstdint>

// ---------------- problem constants ----------------
#define BATCH    64
#define INCH     8192
#define OUTCH    8192
#define NT       64             // out-channel tile per CTA
#define KT       64             // K tile (64 fp16 = 128B row)
#define NITER    (INCH / KT)    // 128
#define NTHREADS 512
#define NCTAS    (OUTCH / NT)   // 128

// W fp32 ring: 4 stages x 64 rows x 320B pitch = 81920
// A fp16 ring: 4 stages x 8192 ; B sign ring: 2 stages x 8192
#define W_PITCH     320
#define W_STAGE     (64 * W_PITCH)
#define SMEM_W      0
#define SMEM_A      (4 * W_STAGE)            // 81920
#define SMEM_B      (SMEM_A + 4 * 8192)      // 114688
#define SMEM_BYTES  (SMEM_B + 2 * 8192)      // 131072

__device__ __half g_xhalf[(size_t)BATCH * INCH];   // fp16 plane of x
__device__ float g_abssum;
__device__ int   g_done;

// ---------------- helpers ----------------
__device__ __forceinline__ uint32_t smem_u32(const void* p) {
    uint32_t a;
    asm("{ .reg .u64 t; cvta.to.shared.u64 t, %1; cvt.u32.u64 %0, t; }" : "=r"(a) : "l"(p));
    return a;
}

#define SW128(off) ((off) ^ (((off) >> 3) & 0x70))

// sign(w) as fp16: +1 / -1 / 0
__device__ __forceinline__ uint32_t sgn_f16(float w) {
    uint32_t u = __float_as_uint(w);
    return (w == 0.0f) ? 0u : (0x3C00u | ((u >> 16) & 0x8000u));
}

__device__ __forceinline__ void ldsm_x4(uint32_t* r, uint32_t addr) {
    asm volatile("ldmatrix.sync.aligned.m8n8.x4.shared.b16 {%0,%1,%2,%3}, [%4];"
                 : "=r"(r[0]), "=r"(r[1]), "=r"(r[2]), "=r"(r[3]) : "r"(addr));
}

__device__ __forceinline__ void mma_f16(float* c, const uint32_t* a, const uint32_t* b) {
    asm volatile(
        "mma.sync.aligned.m16n8k16.row.col.f32.f16.f16.f32 "
        "{%0,%1,%2,%3}, {%4,%5,%6,%7}, {%8,%9}, {%0,%1,%2,%3};"
        : "+f"(c[0]), "+f"(c[1]), "+f"(c[2]), "+f"(c[3])
        : "r"(a[0]), "r"(a[1]), "r"(a[2]), "r"(a[3]), "r"(b[0]), "r"(b[1]));
}

__device__ __forceinline__ void cp_async16(uint32_t dst, const void* src) {
    asm volatile("cp.async.cg.shared.global [%0], [%1], 16;"
                 :: "r"(dst), "l"(__cvta_generic_to_global(src)) : "memory");
}
#define CP_COMMIT() asm volatile("cp.async.commit_group;" ::: "memory")
#define CP_WAIT(n)  asm volatile("cp.async.wait_group %0;" :: "n"(n) : "memory")

// ---------------- kernel 0: x -> fp16 plane, reset globals ----------------
__global__ void hb_split_kernel(const float* __restrict__ x) {
    int i = blockIdx.x * blockDim.x + threadIdx.x;   // over float2 chunks (262144)
    if (i == 0) { g_abssum = 0.0f; g_done = 0; }
    float2 v = reinterpret_cast<const float2*>(x)[i];
    reinterpret_cast<__half2*>(g_xhalf)[i] = __floats2half2_rn(v.x, v.y);
}

// ---------------- kernel 1: fused sign + GEMM + |W| reduce + scale ----------------
__global__ void __launch_bounds__(NTHREADS, 1)
hb_gemm_kernel(const float* __restrict__ W, float* __restrict__ out) {
    extern __shared__ __align__(1024) char smem[];
    const uint32_t sb = smem_u32(smem);

    const int tid  = threadIdx.x;
    const int lane = tid & 31;
    const int wid  = tid >> 5;          // 0..15
    const int wn   = wid & 1;           // 2 warps along N (n32)
    const int wm   = (wid >> 1) & 1;    // 2 warps along M (m32)
    const int kh   = wid >> 2;          // 4 k16-quarters
    const int n0   = blockIdx.x * NT;
    const int nw   = wn * 32;
    const int mwr  = wm * 32;

#define W_OFF(s) (sb + SMEM_W + (uint32_t)(s) * W_STAGE)
#define A_OFF(s) (sb + SMEM_A + (uint32_t)(s) * 8192u)
#define B_OFF(s) (sb + SMEM_B + (uint32_t)(s) * 8192u)

    float c[2][4][4];                   // [m-tile][n-tile][frag], warp tile m32 x n32
#pragma unroll
    for (int mt = 0; mt < 2; mt++)
#pragma unroll
        for (int nt = 0; nt < 4; nt++)
#pragma unroll
            for (int r = 0; r < 4; r++) c[mt][nt][r] = 0.0f;

    float absacc = 0.0f;

    // ldmatrix per-lane coordinates
    const int ar    = lane & 15;
    const int ac8   = lane >> 4;
    const int brow0 = nw +      (lane & 7) + ((lane >> 4) << 3);
    const int brow1 = nw + 16 + (lane & 7) + ((lane >> 4) << 3);
    const int bc8   = (lane >> 3) & 1;

    // W cp.async coords: 2 x 16B per thread (64 rows x 16 chunks = 1024)
    int wr2[2], wc2[2];
#pragma unroll
    for (int g = 0; g < 2; g++) { int cid = tid + g * NTHREADS; wr2[g] = cid >> 4; wc2[g] = cid & 15; }
    // A cp.async coords: 1 x 16B per thread (64 rows x 8 chunks = 512)
    const int xr = tid >> 3, xc = tid & 7;
    // convert-pass coords: thread handles 8 floats (eighth-row)
    const int crow = tid >> 3;
    const int cqc  = tid & 7;

#define CPW(it, st) do { \
    int _k0 = (it) * KT; \
    _Pragma("unroll") \
    for (int g = 0; g < 2; g++) \
        cp_async16(W_OFF(st) + (uint32_t)(wr2[g] * W_PITCH + wc2[g] * 16), \
                   W + (size_t)(n0 + wr2[g]) * INCH + _k0 + wc2[g] * 4); \
} while (0)

#define CPA(it, st) do { \
    int _k0 = (it) * KT; \
    cp_async16(A_OFF(st) + SW128((uint32_t)(xr * 128 + xc * 16)), \
               g_xhalf + (size_t)xr * INCH + _k0 + xc * 8); \
} while (0)

#define CONVERT(st, bp) do { \
    const uint32_t _W = W_OFF(st) + (uint32_t)(crow * W_PITCH + cqc * 32); \
    const uint32_t _B = B_OFF(bp); \
    float f[8]; \
    _Pragma("unroll") \
    for (int j = 0; j < 2; j++) \
        asm volatile("ld.shared.v4.f32 {%0,%1,%2,%3}, [%4];" \
                     : "=f"(f[4*j]), "=f"(f[4*j+1]), "=f"(f[4*j+2]), "=f"(f[4*j+3]) \
                     : "r"(_W + j * 16)); \
    _Pragma("unroll") \
    for (int j = 0; j < 8; j++) absacc += fabsf(f[j]); \
    uint32_t p[4]; \
    _Pragma("unroll") \
    for (int j = 0; j < 4; j++) p[j] = sgn_f16(f[2*j]) | (sgn_f16(f[2*j+1]) << 16); \
    asm volatile("st.shared.v4.b32 [%0], {%1,%2,%3,%4};" \
                 :: "r"(_B + SW128((uint32_t)(crow * 128 + cqc * 16))), \
                    "r"(p[0]), "r"(p[1]), "r"(p[2]), "r"(p[3]) : "memory"); \
} while (0)

#define COMPUTE(st, bp) do { \
    const uint32_t _A = A_OFF(st), _B = B_OFF(bp); \
    uint32_t af[8], bf[8]; \
    ldsm_x4(bf,     _B + SW128((uint32_t)(brow0 * 128 + kh * 32 + bc8 * 16))); \
    ldsm_x4(bf + 4, _B + SW128((uint32_t)(brow1 * 128 + kh * 32 + bc8 * 16))); \
    ldsm_x4(af,     _A + SW128((uint32_t)((mwr + ar) * 128 + kh * 32 + ac8 * 16))); \
    ldsm_x4(af + 4, _A + SW128((uint32_t)((mwr + 16 + ar) * 128 + kh * 32 + ac8 * 16))); \
    _Pragma("unroll") \
    for (int mt = 0; mt < 2; mt++) { \
        mma_f16(c[mt][0], af + 4 * mt, bf); \
        mma_f16(c[mt][1], af + 4 * mt, bf + 2); \
        mma_f16(c[mt][2], af + 4 * mt, bf + 4); \
        mma_f16(c[mt][3], af + 4 * mt, bf + 6); \
    } \
} while (0)

    // ---- prologue: stages 0..2 in flight ----
    CPW(0, 0); CPA(0, 0); CP_COMMIT();
    CPW(1, 1); CPA(1, 1); CP_COMMIT();
    CPW(2, 2); CPA(2, 2); CP_COMMIT();
    CP_WAIT(2);                 // stage 0 resident
    __syncthreads();
    CONVERT(0, 0);              // W0 -> Bsign(0)

    // ---- main loop: one sync per iter ----
    int ws = 3, rcur = 0;
    uint32_t bpar = 0;
    for (int it = 0; it < NITER; ++it) {
        int rs1 = (rcur + 1) & 3;
        if (it + 3 < NITER) {
            CPW(it + 3, ws); CPA(it + 3, ws); CP_COMMIT();
            ws = (ws + 1) & 3;
        }
        if (it + 3 < NITER)      CP_WAIT(2);
        else if (it + 2 < NITER) CP_WAIT(1);
        else                     CP_WAIT(0);
        __syncthreads();
        if (it + 1 < NITER) CONVERT(rs1, bpar ^ 1u);
        COMPUTE(rcur, bpar);
        rcur = rs1; bpar ^= 1u;
    }

    // ---- |W| reduce: warp -> CTA ----
#pragma unroll
    for (int o = 16; o > 0; o >>= 1) absacc += __shfl_xor_sync(0xFFFFFFFFu, absacc, o);
    __syncthreads();  // rings dead; smem reused below
    float* comb = reinterpret_cast<float*>(smem);           // 3 x 4096 floats (48KB)
    float* wsum = reinterpret_cast<float*>(smem + 64512);   // 16 floats
    if (lane == 0) wsum[wid] = absacc;

    // ---- kh>0 warps publish partial accumulators (own 32x32 quadrant) ----
    if (kh > 0) {
        float* blk = comb + (kh - 1) * 4096;
#pragma unroll
        for (int mt = 0; mt < 2; mt++)
#pragma unroll
            for (int nt = 0; nt < 4; nt++) {
                int r0 = mwr + mt * 16 + (lane >> 2);
                int cl = nw + nt * 8 + (lane & 3) * 2;
                blk[r0 * 64 + cl]           = c[mt][nt][0];
                blk[r0 * 64 + cl + 1]       = c[mt][nt][1];
                blk[(r0 + 8) * 64 + cl]     = c[mt][nt][2];
                blk[(r0 + 8) * 64 + cl + 1] = c[mt][nt][3];
            }
    }
    __syncthreads();

    // ---- global barrier across all CTAs, then pick up final abs-sum ----
    if (tid == 0) {
        float ctasum = 0.0f;
#pragma unroll
        for (int j = 0; j < 16; j++) ctasum += wsum[j];
        atomicAdd(&g_abssum, ctasum);
        __threadfence();
        atomicAdd(&g_done, 1);
        while (*((volatile int*)&g_done) < NCTAS) __nanosleep(64);
    }
    __syncthreads();
    const float s = (*((volatile float*)&g_abssum)) * (1.0f / ((float)INCH * (float)OUTCH));

    // ---- kh==0 warps combine 3 partials, scale, store ----
    if (kh == 0) {
#pragma unroll
        for (int mt = 0; mt < 2; mt++)
#pragma unroll
            for (int nt = 0; nt < 4; nt++) {
                int r0 = mwr + mt * 16 + (lane >> 2);
                int cl = nw + nt * 8 + (lane & 3) * 2;
                float v0 = c[mt][nt][0], v1 = c[mt][nt][1];
                float v2 = c[mt][nt][2], v3 = c[mt][nt][3];
#pragma unroll
                for (int q = 0; q < 3; q++) {
                    const float* blk = comb + q * 4096;
                    v0 += blk[r0 * 64 + cl];
                    v1 += blk[r0 * 64 + cl + 1];
                    v2 += blk[(r0 + 8) * 64 + cl];
                    v3 += blk[(r0 + 8) * 64 + cl + 1];
                }
                *reinterpret_cast<float2*>(out + (size_t)r0 * OUTCH + n0 + cl) =
                    make_float2(v0 * s, v1 * s);
                *reinterpret_cast<float2*>(out + (size_t)(r0 + 8) * OUTCH + n0 + cl) =
                    make_float2(v2 * s, v3 * s);
            }
    }

#undef CPW
#undef CPA
#undef CONVERT
#undef COMPUTE
#undef W_OFF
#undef A_OFF
#undef B_OFF
}

// ---------------- launch ----------------
extern "C" void kernel_launch(void* const* d_in, const int* in_sizes, int n_in,
                              void* d_out, int out_size) {
    const float* x = (const float*)d_in[0];
    const float* w = (const float*)d_in[1];
    if (n_in >= 2 && in_sizes[0] != BATCH * INCH) { const float* t = x; x = w; w = t; }
    float* out = (float*)d_out;

    cudaFuncSetAttribute(hb_gemm_kernel,
                         cudaFuncAttributeMaxDynamicSharedMemorySize, SMEM_BYTES);

    hb_split_kernel<<<(BATCH * INCH / 2) / 256, 256>>>(x);
    hb_gemm_kernel<<<NCTAS, NTHREADS, SMEM_BYTES>>>(w, out);
}